// round 1
// baseline (speedup 1.0000x reference)
#include <cuda_runtime.h>
#include <cstdint>
#include <cstddef>

#define BATCH 8
#define CCH   512
#define M2    1024          // 2*C rows of P
#define KDIM  4096
#define NTILES 8            // M2 / BM
#define BM    128
#define BK    8
#define SPAD  132           // padded smem row stride (floats); 132*4=528 B, 16B-aligned

// ---------------- scratch (static device globals; no allocation) ----------------
__device__ float          g_S[(size_t)BATCH * M2 * M2];        // 32 MB  S = P P^T
__device__ float          g_w[(size_t)BATCH * CCH * CCH];      // 8 MB   compact weights
__device__ unsigned short g_idx[(size_t)BATCH * CCH * CCH];    // 4 MB   compact indices
__device__ int            g_cnt[BATCH * CCH];

typedef unsigned long long ull;

__device__ __forceinline__ ull pack2(float lo, float hi) {
    ull r; asm("mov.b64 %0, {%1,%2};" : "=l"(r) : "f"(lo), "f"(hi)); return r;
}
__device__ __forceinline__ void unpack2(float& lo, float& hi, ull v) {
    asm("mov.b64 {%0,%1}, %2;" : "=f"(lo), "=f"(hi) : "l"(v));
}
__device__ __forceinline__ void ffma2(ull& d, ull a, ull b) {
    asm("fma.rn.f32x2 %0, %1, %2, %3;" : "=l"(d) : "l"(a), "l"(b), "l"(d));
}

// =======================================================================
// Kernel A: batched symmetric S = P P^T, upper-triangle tiles + mirror.
// P rows 0..511 = qr channels, 512..1023 = qi channels (both straight from x).
// 128x128 tile per block, BK=8, 256 threads, 8x8 per thread via f32x2 FMA.
// =======================================================================
__global__ __launch_bounds__(256, 2) void syrk_kernel(const float* __restrict__ x) {
    __shared__ float As[2][BK * SPAD];
    __shared__ float Bs[2][BK * SPAD];

    const int b = blockIdx.y;
    int t = blockIdx.x;
    int ti = 0, rem = t;
    while (rem >= NTILES - ti) { rem -= NTILES - ti; ti++; }
    const int tj = ti + rem;

    const int tid = threadIdx.x;
    const int tx = tid & 15;       // n-dim
    const int ty = tid >> 4;       // m-dim

    // global-load assignment: each thread loads one float4 of A and of B per stage
    const int lrow = tid >> 1;            // 0..127
    const int lk   = (tid & 1) * 4;       // 0 or 4

    const int mA = ti * BM + lrow;
    const int mB = tj * BM + lrow;
    // x layout (2,B,C,N): real row c at (b*C+c)*N ; imag at ((BATCH+b)*C+c)*N
    const float* Abase = x + ((size_t)b * CCH + mA + (mA >= CCH ? (size_t)(BATCH - 1) * CCH : 0)) * KDIM + lk;
    const float* Bbase = x + ((size_t)b * CCH + mB + (mB >= CCH ? (size_t)(BATCH - 1) * CCH : 0)) * KDIM + lk;

    ull acc[8][4];
    #pragma unroll
    for (int m = 0; m < 8; m++)
        #pragma unroll
        for (int p = 0; p < 4; p++) acc[m][p] = 0ull;

    // stage 0
    {
        float4 ra = *(const float4*)Abase;
        float4 rb = *(const float4*)Bbase;
        float av[4] = {ra.x, ra.y, ra.z, ra.w};
        float bv[4] = {rb.x, rb.y, rb.z, rb.w};
        #pragma unroll
        for (int j = 0; j < 4; j++) {
            As[0][(lk + j) * SPAD + lrow] = av[j];
            Bs[0][(lk + j) * SPAD + lrow] = bv[j];
        }
    }
    __syncthreads();

    int buf = 0;
    const int NS = KDIM / BK;      // 512 stages
    for (int kb = 0; kb < NS; kb++) {
        float4 na, nb;
        const bool more = (kb + 1 < NS);
        if (more) {
            na = *(const float4*)(Abase + (size_t)(kb + 1) * BK);
            nb = *(const float4*)(Bbase + (size_t)(kb + 1) * BK);
        }
        const float* Ab = As[buf];
        const float* Bb = Bs[buf];
        #pragma unroll
        for (int k = 0; k < BK; k++) {
            float4 a0 = *(const float4*)(Ab + k * SPAD + ty * 4);
            float4 a1 = *(const float4*)(Ab + k * SPAD + 64 + ty * 4);
            ulonglong2 b0 = *(const ulonglong2*)(Bb + k * SPAD + tx * 4);
            ulonglong2 b1 = *(const ulonglong2*)(Bb + k * SPAD + 64 + tx * 4);
            float a_[8] = {a0.x, a0.y, a0.z, a0.w, a1.x, a1.y, a1.z, a1.w};
            ull bp0 = b0.x, bp1 = b0.y, bp2 = b1.x, bp3 = b1.y;
            #pragma unroll
            for (int m = 0; m < 8; m++) {
                ull am = pack2(a_[m], a_[m]);
                ffma2(acc[m][0], am, bp0);
                ffma2(acc[m][1], am, bp1);
                ffma2(acc[m][2], am, bp2);
                ffma2(acc[m][3], am, bp3);
            }
        }
        if (more) {
            float av[4] = {na.x, na.y, na.z, na.w};
            float bv[4] = {nb.x, nb.y, nb.z, nb.w};
            const int nbuf = buf ^ 1;
            #pragma unroll
            for (int j = 0; j < 4; j++) {
                As[nbuf][(lk + j) * SPAD + lrow] = av[j];
                Bs[nbuf][(lk + j) * SPAD + lrow] = bv[j];
            }
        }
        __syncthreads();
        buf ^= 1;
    }

    // epilogue
    float cv[8][8];
    #pragma unroll
    for (int m = 0; m < 8; m++)
        #pragma unroll
        for (int p = 0; p < 4; p++) unpack2(cv[m][2 * p], cv[m][2 * p + 1], acc[m][p]);

    const size_t Sb = (size_t)b * M2 * M2;
    const int r0 = ti * BM, c0 = tj * BM;
    #pragma unroll
    for (int m = 0; m < 8; m++) {
        const int row = r0 + (m >> 2) * 64 + ty * 4 + (m & 3);
        float4 v0 = make_float4(cv[m][0], cv[m][1], cv[m][2], cv[m][3]);
        float4 v1 = make_float4(cv[m][4], cv[m][5], cv[m][6], cv[m][7]);
        *(float4*)&g_S[Sb + (size_t)row * M2 + c0 + tx * 4]      = v0;
        *(float4*)&g_S[Sb + (size_t)row * M2 + c0 + 64 + tx * 4] = v1;
    }
    if (ti != tj) {   // mirror into lower triangle
        #pragma unroll
        for (int m = 0; m < 8; m++) {
            const int row = r0 + (m >> 2) * 64 + ty * 4 + (m & 3);
            #pragma unroll
            for (int n = 0; n < 8; n++) {
                const int col = c0 + (n < 4 ? tx * 4 + n : 64 + tx * 4 + (n - 4));
                g_S[Sb + (size_t)col * M2 + row] = cv[m][n];
            }
        }
    }
}

// =======================================================================
// Kernel B: per (b,c) row: er/ei from S, row maxes, softmax of er2^2+ei2^2,
// deterministic ballot-scan compaction of weights > 1e-10.
// =======================================================================
__device__ __forceinline__ float blkReduce(float v, float* red, bool isMax) {
    #pragma unroll
    for (int o = 16; o > 0; o >>= 1) {
        float tv = __shfl_xor_sync(0xffffffffu, v, o);
        v = isMax ? fmaxf(v, tv) : (v + tv);
    }
    const int lane = threadIdx.x & 31, wid = threadIdx.x >> 5;
    if (lane == 0) red[wid] = v;
    __syncthreads();
    if (wid == 0) {
        float tv = (lane < 16) ? red[lane] : (isMax ? -3.4e38f : 0.0f);
        #pragma unroll
        for (int o = 8; o > 0; o >>= 1) {
            float u = __shfl_xor_sync(0xffffffffu, tv, o);
            tv = isMax ? fmaxf(tv, u) : (tv + u);
        }
        if (lane == 0) red[0] = tv;
    }
    __syncthreads();
    const float res = red[0];
    __syncthreads();
    return res;
}

__global__ void attn_kernel() {
    __shared__ float red[16];
    __shared__ int wcnt[16];
    __shared__ int woff[16];

    const int r = blockIdx.x;
    const int b = r >> 9, c = r & 511;
    const int d = threadIdx.x;
    const int lane = d & 31, wid = d >> 5;

    const float* S0 = g_S + ((size_t)b * M2 + c) * M2;
    const float* S1 = g_S + ((size_t)b * M2 + CCH + c) * M2;

    const float er = S0[d] - S1[CCH + d];          // rr - ii
    const float ei = S0[CCH + d] + S1[d];          // ri + ir

    const float mer = blkReduce(er, red, true);
    const float mei = blkReduce(ei, red, true);

    const float ar = mer - er;
    const float ai = mei - ei;
    const float s = ar * ar + ai * ai;

    const float smax = blkReduce(s, red, true);
    const float e = expf(s - smax);
    const float Z = blkReduce(e, red, false);
    const float w = e / Z;

    const bool keep = w > 1e-10f;
    const unsigned msk = __ballot_sync(0xffffffffu, keep);
    const int inpos = __popc(msk & ((1u << lane) - 1u));
    if (lane == 0) wcnt[wid] = __popc(msk);
    __syncthreads();
    if (d == 0) {
        int run = 0;
        #pragma unroll
        for (int i = 0; i < 16; i++) { woff[i] = run; run += wcnt[i]; }
        g_cnt[r] = run;
    }
    __syncthreads();
    if (keep) {
        const int pos = woff[wid] + inpos;
        g_idx[(size_t)r * CCH + pos] = (unsigned short)d;
        g_w[(size_t)r * CCH + pos] = w;
    }
}

// =======================================================================
// Kernel C: out = gamma * (sparse attention @ q) + x   (both components)
// =======================================================================
__global__ __launch_bounds__(256) void apply_kernel(const float* __restrict__ x,
                                                    const float* __restrict__ gamma,
                                                    float* __restrict__ out) {
    const int r = blockIdx.x;
    const int b = r >> 9, c = r & 511;
    const int n = blockIdx.y * 1024 + threadIdx.x * 4;

    const int cnt = g_cnt[r];
    const float g = gamma[0];
    const size_t imagOff = (size_t)BATCH * CCH * KDIM;
    const float* xr = x;
    const float* xi = x + imagOff;

    float4 ar = make_float4(0.f, 0.f, 0.f, 0.f);
    float4 ai = make_float4(0.f, 0.f, 0.f, 0.f);
    const size_t lbase = (size_t)r * CCH;

    for (int i = 0; i < cnt; i++) {
        const int dch = g_idx[lbase + i];
        const float w = g_w[lbase + i];
        const size_t q = ((size_t)b * CCH + dch) * KDIM + n;
        const float4 qr = *(const float4*)(xr + q);
        const float4 qi = *(const float4*)(xi + q);
        ar.x += w * qr.x; ar.y += w * qr.y; ar.z += w * qr.z; ar.w += w * qr.w;
        ai.x += w * qi.x; ai.y += w * qi.y; ai.z += w * qi.z; ai.w += w * qi.w;
    }

    const size_t o = ((size_t)b * CCH + c) * KDIM + n;
    const float4 xrv = *(const float4*)(xr + o);
    const float4 xiv = *(const float4*)(xi + o);
    float4 orr = make_float4(g * ar.x + xrv.x, g * ar.y + xrv.y,
                             g * ar.z + xrv.z, g * ar.w + xrv.w);
    float4 oii = make_float4(g * ai.x + xiv.x, g * ai.y + xiv.y,
                             g * ai.z + xiv.z, g * ai.w + xiv.w);
    *(float4*)(out + o) = orr;
    *(float4*)(out + imagOff + o) = oii;
}

// =======================================================================
extern "C" void kernel_launch(void* const* d_in, const int* in_sizes, int n_in,
                              void* d_out, int out_size) {
    const float* x = (const float*)d_in[0];
    const float* gamma = (const float*)d_in[1];
    float* out = (float*)d_out;

    syrk_kernel<<<dim3(NTILES * (NTILES + 1) / 2, BATCH), 256>>>(x);
    attn_kernel<<<BATCH * CCH, 512>>>();
    apply_kernel<<<dim3(BATCH * CCH, 4), 256>>>(x, gamma, out);
}

// round 3
// speedup vs baseline: 2.7656x; 2.7656x over previous
#include <cuda_runtime.h>
#include <cstdint>
#include <cstddef>

#define BATCH 8
#define CCH   512
#define M2    1024          // 2*C rows of P
#define KDIM  4096
#define NTILES 8            // M2 / 128
#define NSTAGES 3
#define TILE_BYTES (128 * 128)         // 16KB: 128 rows x 128B (32 tf32), SW128 image
#define STAGE_BYTES (4 * TILE_BYTES)   // Ahi, Alo, Bhi, Blo
#define NKB   (KDIM / 32)              // 128 k-blocks of 32 tf32

// idesc kind::tf32: dtype F32 (1<<4) | atype TF32 (2<<7) | btype TF32 (2<<10)
//                 | (N/8)<<17 | (M/16)<<24, K-major both sides
#define IDESC_TF32 0x08200910u

// Arch-specific ('a') feature gate: tcgen05 only exists in the sm_103a/sm_100a
// SASS pass; the harness's generic compute_103 PTX pass must not see it.
#if defined(__CUDA_ARCH__) && (defined(__CUDA_ARCH_FEAT_SM103_ALL) || defined(__CUDA_ARCH_FEAT_SM100_ALL) || defined(__CUDA_ARCH_FEAT_SM101_ALL) || defined(__CUDA_ARCH_FEAT_SM110_ALL))
#define TC_OK 1
#else
#define TC_OK 0
#endif

// ---------------- scratch (static device globals; no allocation) ----------------
__device__ float          g_hi[(size_t)BATCH * 8 * NKB * 4096];   // 134 MB
__device__ float          g_lo[(size_t)BATCH * 8 * NKB * 4096];   // 134 MB
__device__ float          g_S[(size_t)BATCH * M2 * M2];           // 32 MB  S = P P^T
__device__ float          g_w[(size_t)BATCH * CCH * CCH];
__device__ unsigned short g_idx[(size_t)BATCH * CCH * CCH];
__device__ int            g_cnt[BATCH * CCH];
__device__ int            g_use_tc;

typedef unsigned long long ull;

// ======================= generic helpers =======================
__device__ __forceinline__ uint32_t smem_u32(const void* p) {
    uint32_t a;
    asm("{ .reg .u64 t; cvta.to.shared.u64 t, %1; cvt.u32.u64 %0, t; }" : "=r"(a) : "l"(p));
    return a;
}
__device__ __forceinline__ ull pack2(float lo, float hi) {
    ull r; asm("mov.b64 %0, {%1,%2};" : "=l"(r) : "f"(lo), "f"(hi)); return r;
}
__device__ __forceinline__ void unpack2(float& lo, float& hi, ull v) {
    asm("mov.b64 {%0,%1}, %2;" : "=f"(lo), "=f"(hi) : "l"(v));
}
__device__ __forceinline__ void ffma2(ull& d, ull a, ull b) {
    asm("fma.rn.f32x2 %0, %1, %2, %3;" : "=l"(d) : "l"(a), "l"(b), "l"(d));
}

// ======================= probe: which image is running? =======================
__global__ void probe_kernel() { g_use_tc = TC_OK; }

// =======================================================================
// Kernel 0: split fp32 -> (tf32 hi, tf32 residual lo), written pre-tiled
// and pre-SW128-swizzled so one cp.async.bulk per 16KB tile feeds the MMA.
// =======================================================================
__global__ __launch_bounds__(256) void split_kernel(const float* __restrict__ x) {
    const size_t idx = (size_t)blockIdx.x * 256 + threadIdx.x;   // 8*1024*1024 float4s
    const int b   = (int)(idx >> 20);
    const int row = (int)((idx >> 10) & 1023);
    const int k4  = (int)(idx & 1023);

    size_t src;
    if (row < CCH) src = ((size_t)b * CCH + row) * KDIM + (size_t)k4 * 4;
    else           src = ((size_t)(BATCH + b) * CCH + (row - CCH)) * KDIM + (size_t)k4 * 4;

    const float4 v = *(const float4*)(x + src);

    float4 hi, lo;
    {
        uint32_t h, l; float r;
        asm("cvt.rna.tf32.f32 %0, %1;" : "=r"(h) : "f"(v.x)); hi.x = __uint_as_float(h);
        r = v.x - hi.x; asm("cvt.rna.tf32.f32 %0, %1;" : "=r"(l) : "f"(r)); lo.x = __uint_as_float(l);
        asm("cvt.rna.tf32.f32 %0, %1;" : "=r"(h) : "f"(v.y)); hi.y = __uint_as_float(h);
        r = v.y - hi.y; asm("cvt.rna.tf32.f32 %0, %1;" : "=r"(l) : "f"(r)); lo.y = __uint_as_float(l);
        asm("cvt.rna.tf32.f32 %0, %1;" : "=r"(h) : "f"(v.z)); hi.z = __uint_as_float(h);
        r = v.z - hi.z; asm("cvt.rna.tf32.f32 %0, %1;" : "=r"(l) : "f"(r)); lo.z = __uint_as_float(l);
        asm("cvt.rna.tf32.f32 %0, %1;" : "=r"(h) : "f"(v.w)); hi.w = __uint_as_float(h);
        r = v.w - hi.w; asm("cvt.rna.tf32.f32 %0, %1;" : "=r"(l) : "f"(r)); lo.w = __uint_as_float(l);
    }

    const int rb = row >> 7, r = row & 127;
    const int kb = k4 >> 3;
    const uint32_t byte_off = (uint32_t)r * 128u + (uint32_t)(k4 & 7) * 16u;
    const uint32_t sw = byte_off ^ ((byte_off >> 3) & 0x70u);
    const size_t dst = ((((size_t)b * 8 + rb) * NKB) + kb) * 4096 + (sw >> 2);

    *(float4*)(g_hi + dst) = hi;
    *(float4*)(g_lo + dst) = lo;
}

// =======================================================================
// Kernel A (tensor path): tcgen05 tf32 3-split SYRK, 128x128 tile per CTA,
// warp-specialized bulk-copy producer + MMA issuer, 3-stage mbarrier ring.
// =======================================================================
#if TC_OK
__device__ __forceinline__ void mbar_init(uint32_t a, uint32_t cnt) {
    asm volatile("mbarrier.init.shared.b64 [%0], %1;" :: "r"(a), "r"(cnt) : "memory");
}
__device__ __forceinline__ void mbar_inval(uint32_t a) {
    asm volatile("mbarrier.inval.shared.b64 [%0];" :: "r"(a) : "memory");
}
__device__ __forceinline__ void mbar_expect_tx(uint32_t a, uint32_t bytes) {
    asm volatile("mbarrier.arrive.expect_tx.shared.b64 _, [%0], %1;" :: "r"(a), "r"(bytes) : "memory");
}
__device__ __forceinline__ void mbar_wait(uint32_t a, uint32_t parity) {
    asm volatile(
        "{\n\t.reg .pred P;\n\t"
        "W%=:\n\t"
        "mbarrier.try_wait.parity.acquire.cta.shared::cta.b64 P, [%0], %1, 0x989680;\n\t"
        "@P bra.uni D%=;\n\t"
        "bra.uni W%=;\n\t"
        "D%=:\n\t}"
        :: "r"(a), "r"(parity) : "memory");
}
__device__ __forceinline__ void bulk_g2s(uint32_t dst, const void* src, uint32_t bytes, uint32_t mbar) {
    asm volatile(
        "cp.async.bulk.shared::cta.global.mbarrier::complete_tx::bytes [%0], [%1], %2, [%3];"
        :: "r"(dst), "l"(src), "r"(bytes), "r"(mbar) : "memory");
}
__device__ __forceinline__ uint64_t make_desc_sw128(uint32_t addr) {
    return ((uint64_t)2 << 61) | ((uint64_t)1 << 46) | ((uint64_t)64 << 32) |
           ((uint64_t)1 << 16) | (((uint64_t)(addr >> 4)) & 0x3FFF);
}
__device__ __forceinline__ void mma_tf32_ss(uint32_t d, uint64_t ad, uint64_t bd, uint32_t en) {
    asm volatile(
        "{\n\t.reg .pred p;\n\t"
        "setp.ne.u32 p, %4, 0;\n\t"
        "tcgen05.mma.cta_group::1.kind::tf32 [%0], %1, %2, %3, {%5,%5,%5,%5}, p;\n\t}"
        :: "r"(d), "l"(ad), "l"(bd), "r"(IDESC_TF32), "r"(en), "r"(0u) : "memory");
}
__device__ __forceinline__ void tc_commit(uint32_t mbar) {
    asm volatile(
        "tcgen05.commit.cta_group::1.mbarrier::arrive::one.shared::cluster.b64 [%0];"
        :: "r"(mbar) : "memory");
}
#endif

__global__ __launch_bounds__(128, 1) void syrk_tc_kernel() {
#if TC_OK
    if (g_use_tc == 0) return;
    extern __shared__ char smem[];
    const uint32_t sb = smem_u32(smem);
    const uint32_t tb = (sb + 1023u) & ~1023u;            // 1024-aligned tile base
    const uint32_t ctl = tb + NSTAGES * STAGE_BYTES;      // control area
    const uint32_t mb_full  = ctl + 16;
    const uint32_t mb_empty = ctl + 16 + 24;
    const uint32_t mb_done  = ctl + 16 + 48;

    const int tid = threadIdx.x;
    const int wid = tid >> 5, lid = tid & 31;

    const int b = blockIdx.y;
    int ti = 0, rem = blockIdx.x;
    while (rem >= NTILES - ti) { rem -= NTILES - ti; ti++; }
    const int tj = ti + rem;
    const bool diag = (ti == tj);

    if (wid == 0) {
        asm volatile("tcgen05.alloc.cta_group::1.sync.aligned.shared::cta.b32 [%0], %1;"
                     :: "r"(ctl), "r"(128u) : "memory");
    }
    if (tid == 0) {
        for (int s = 0; s < NSTAGES; s++) { mbar_init(mb_full + s * 8, 1); mbar_init(mb_empty + s * 8, 1); }
        mbar_init(mb_done, 1);
        asm volatile("fence.proxy.async.shared::cta;" ::: "memory");
    }
    __syncthreads();

    uint32_t tmem;
    asm volatile("ld.shared.b32 %0, [%1];" : "=r"(tmem) : "r"(ctl));

    const uint32_t txbytes = diag ? (2 * TILE_BYTES) : (4 * TILE_BYTES);

    if (tid == 0) {
        // ---------------- producer ----------------
        const size_t tiA = (((size_t)b * 8 + ti) * NKB) * 4096;
        const size_t tiB = (((size_t)b * 8 + tj) * NKB) * 4096;
        int ph[NSTAGES] = {0, 0, 0};
        for (int kb = 0; kb < NKB; kb++) {
            const int s = kb % NSTAGES;
            if (kb >= NSTAGES) { mbar_wait(mb_empty + s * 8, ph[s]); ph[s] ^= 1; }
            const uint32_t st = tb + s * STAGE_BYTES;
            const uint32_t fb = mb_full + s * 8;
            mbar_expect_tx(fb, txbytes);
            bulk_g2s(st,                  g_hi + tiA + (size_t)kb * 4096, TILE_BYTES, fb);
            bulk_g2s(st + TILE_BYTES,     g_lo + tiA + (size_t)kb * 4096, TILE_BYTES, fb);
            if (!diag) {
                bulk_g2s(st + 2 * TILE_BYTES, g_hi + tiB + (size_t)kb * 4096, TILE_BYTES, fb);
                bulk_g2s(st + 3 * TILE_BYTES, g_lo + tiB + (size_t)kb * 4096, TILE_BYTES, fb);
            }
        }
    } else if (tid == 32) {
        // ---------------- MMA issuer ----------------
        int ph[NSTAGES] = {0, 0, 0};
        uint32_t en = 0;
        for (int kb = 0; kb < NKB; kb++) {
            const int s = kb % NSTAGES;
            mbar_wait(mb_full + s * 8, ph[s]); ph[s] ^= 1;
            const uint32_t st = tb + s * STAGE_BYTES;
            const uint64_t dAh = make_desc_sw128(st);
            const uint64_t dAl = make_desc_sw128(st + TILE_BYTES);
            const uint64_t dBh = diag ? dAh : make_desc_sw128(st + 2 * TILE_BYTES);
            const uint64_t dBl = diag ? dAl : make_desc_sw128(st + 3 * TILE_BYTES);
            #pragma unroll
            for (int k = 0; k < 4; k++) {           // 4 k-steps of 8 tf32
                mma_tf32_ss(tmem, dAh + k * 2, dBh + k * 2, en); en = 1;
                mma_tf32_ss(tmem, dAh + k * 2, dBl + k * 2, 1);
                mma_tf32_ss(tmem, dAl + k * 2, dBh + k * 2, 1);
            }
            tc_commit(mb_empty + s * 8);
        }
        tc_commit(mb_done);
    }

    // ---------------- epilogue ----------------
    mbar_wait(mb_done, 0);
    asm volatile("tcgen05.fence::after_thread_sync;" ::: "memory");

    const size_t Sb = (size_t)b * M2 * M2;
    const int r0 = ti * 128, c0 = tj * 128;
    const int row = r0 + wid * 32 + lid;

    for (int cb = 0; cb < 4; cb++) {
        uint32_t d[32];
        asm volatile(
            "tcgen05.ld.sync.aligned.32x32b.x32.b32 "
            "{%0,%1,%2,%3,%4,%5,%6,%7,%8,%9,%10,%11,%12,%13,%14,%15,"
            "%16,%17,%18,%19,%20,%21,%22,%23,%24,%25,%26,%27,%28,%29,%30,%31}, [%32];"
            : "=r"(d[0]), "=r"(d[1]), "=r"(d[2]), "=r"(d[3]), "=r"(d[4]), "=r"(d[5]), "=r"(d[6]), "=r"(d[7]),
              "=r"(d[8]), "=r"(d[9]), "=r"(d[10]), "=r"(d[11]), "=r"(d[12]), "=r"(d[13]), "=r"(d[14]), "=r"(d[15]),
              "=r"(d[16]), "=r"(d[17]), "=r"(d[18]), "=r"(d[19]), "=r"(d[20]), "=r"(d[21]), "=r"(d[22]), "=r"(d[23]),
              "=r"(d[24]), "=r"(d[25]), "=r"(d[26]), "=r"(d[27]), "=r"(d[28]), "=r"(d[29]), "=r"(d[30]), "=r"(d[31])
            : "r"(tmem + cb * 32));
        asm volatile("tcgen05.wait::ld.sync.aligned;" ::: "memory");

        float* dst = g_S + Sb + (size_t)row * M2 + c0 + cb * 32;
        #pragma unroll
        for (int q = 0; q < 8; q++) {
            float4 v = make_float4(__uint_as_float(d[q * 4 + 0]), __uint_as_float(d[q * 4 + 1]),
                                   __uint_as_float(d[q * 4 + 2]), __uint_as_float(d[q * 4 + 3]));
            *(float4*)(dst + q * 4) = v;
        }
        if (!diag) {
            #pragma unroll
            for (int j = 0; j < 32; j++)
                g_S[Sb + (size_t)(c0 + cb * 32 + j) * M2 + row] = __uint_as_float(d[j]);
        }
    }

    __syncthreads();
    if (tid == 0) {
        for (int s = 0; s < NSTAGES; s++) { mbar_inval(mb_full + s * 8); mbar_inval(mb_empty + s * 8); }
        mbar_inval(mb_done);
    }
    __syncthreads();
    if (wid == 0) {
        asm volatile("tcgen05.dealloc.cta_group::1.sync.aligned.b32 %0, %1;" :: "r"(tmem), "r"(128u));
    }
#endif
}

// =======================================================================
// Kernel A' (fallback path): R1 FFMA2 SIMT SYRK. Runs only if g_use_tc==0.
// =======================================================================
#define BK    8
#define SPAD  132
__global__ __launch_bounds__(256, 2) void syrk_simt_kernel(const float* __restrict__ x) {
    if (g_use_tc != 0) return;
    __shared__ float As[2][BK * SPAD];
    __shared__ float Bs[2][BK * SPAD];

    const int b = blockIdx.y;
    int t = blockIdx.x;
    int ti = 0, rem = t;
    while (rem >= NTILES - ti) { rem -= NTILES - ti; ti++; }
    const int tj = ti + rem;

    const int tid = threadIdx.x;
    const int tx = tid & 15;
    const int ty = tid >> 4;
    const int lrow = tid >> 1;
    const int lk   = (tid & 1) * 4;

    const int mA = ti * 128 + lrow;
    const int mB = tj * 128 + lrow;
    const float* Abase = x + ((size_t)b * CCH + mA + (mA >= CCH ? (size_t)(BATCH - 1) * CCH : 0)) * KDIM + lk;
    const float* Bbase = x + ((size_t)b * CCH + mB + (mB >= CCH ? (size_t)(BATCH - 1) * CCH : 0)) * KDIM + lk;

    ull acc[8][4];
    #pragma unroll
    for (int m = 0; m < 8; m++)
        #pragma unroll
        for (int p = 0; p < 4; p++) acc[m][p] = 0ull;

    {
        float4 ra = *(const float4*)Abase;
        float4 rb = *(const float4*)Bbase;
        float av[4] = {ra.x, ra.y, ra.z, ra.w};
        float bv[4] = {rb.x, rb.y, rb.z, rb.w};
        #pragma unroll
        for (int j = 0; j < 4; j++) {
            As[0][(lk + j) * SPAD + lrow] = av[j];
            Bs[0][(lk + j) * SPAD + lrow] = bv[j];
        }
    }
    __syncthreads();

    int buf = 0;
    const int NS = KDIM / BK;
    for (int kb = 0; kb < NS; kb++) {
        float4 na, nb;
        const bool more = (kb + 1 < NS);
        if (more) {
            na = *(const float4*)(Abase + (size_t)(kb + 1) * BK);
            nb = *(const float4*)(Bbase + (size_t)(kb + 1) * BK);
        }
        const float* Ab = As[buf];
        const float* Bb = Bs[buf];
        #pragma unroll
        for (int k = 0; k < BK; k++) {
            float4 a0 = *(const float4*)(Ab + k * SPAD + ty * 4);
            float4 a1 = *(const float4*)(Ab + k * SPAD + 64 + ty * 4);
            ulonglong2 b0 = *(const ulonglong2*)(Bb + k * SPAD + tx * 4);
            ulonglong2 b1 = *(const ulonglong2*)(Bb + k * SPAD + 64 + tx * 4);
            float a_[8] = {a0.x, a0.y, a0.z, a0.w, a1.x, a1.y, a1.z, a1.w};
            ull bp0 = b0.x, bp1 = b0.y, bp2 = b1.x, bp3 = b1.y;
            #pragma unroll
            for (int m = 0; m < 8; m++) {
                ull am = pack2(a_[m], a_[m]);
                ffma2(acc[m][0], am, bp0);
                ffma2(acc[m][1], am, bp1);
                ffma2(acc[m][2], am, bp2);
                ffma2(acc[m][3], am, bp3);
            }
        }
        if (more) {
            float av[4] = {na.x, na.y, na.z, na.w};
            float bv[4] = {nb.x, nb.y, nb.z, nb.w};
            const int nbuf = buf ^ 1;
            #pragma unroll
            for (int j = 0; j < 4; j++) {
                As[nbuf][(lk + j) * SPAD + lrow] = av[j];
                Bs[nbuf][(lk + j) * SPAD + lrow] = bv[j];
            }
        }
        __syncthreads();
        buf ^= 1;
    }

    float cv[8][8];
    #pragma unroll
    for (int m = 0; m < 8; m++)
        #pragma unroll
        for (int p = 0; p < 4; p++) unpack2(cv[m][2 * p], cv[m][2 * p + 1], acc[m][p]);

    const size_t Sb = (size_t)b * M2 * M2;
    const int r0 = ti * 128, c0 = tj * 128;
    #pragma unroll
    for (int m = 0; m < 8; m++) {
        const int row = r0 + (m >> 2) * 64 + ty * 4 + (m & 3);
        float4 v0 = make_float4(cv[m][0], cv[m][1], cv[m][2], cv[m][3]);
        float4 v1 = make_float4(cv[m][4], cv[m][5], cv[m][6], cv[m][7]);
        *(float4*)&g_S[Sb + (size_t)row * M2 + c0 + tx * 4]      = v0;
        *(float4*)&g_S[Sb + (size_t)row * M2 + c0 + 64 + tx * 4] = v1;
    }
    if (ti != tj) {
        #pragma unroll
        for (int m = 0; m < 8; m++) {
            const int row = r0 + (m >> 2) * 64 + ty * 4 + (m & 3);
            #pragma unroll
            for (int n = 0; n < 8; n++) {
                const int col = c0 + (n < 4 ? tx * 4 + n : 64 + tx * 4 + (n - 4));
                g_S[Sb + (size_t)col * M2 + row] = cv[m][n];
            }
        }
    }
}

// =======================================================================
// Kernel B: softmax of (max-er)^2+(max-ei)^2 over S rows + compaction
// =======================================================================
__device__ __forceinline__ float blkReduce(float v, float* red, bool isMax) {
    #pragma unroll
    for (int o = 16; o > 0; o >>= 1) {
        float tv = __shfl_xor_sync(0xffffffffu, v, o);
        v = isMax ? fmaxf(v, tv) : (v + tv);
    }
    const int lane = threadIdx.x & 31, wid = threadIdx.x >> 5;
    if (lane == 0) red[wid] = v;
    __syncthreads();
    if (wid == 0) {
        float tv = (lane < 16) ? red[lane] : (isMax ? -3.4e38f : 0.0f);
        #pragma unroll
        for (int o = 8; o > 0; o >>= 1) {
            float u = __shfl_xor_sync(0xffffffffu, tv, o);
            tv = isMax ? fmaxf(tv, u) : (tv + u);
        }
        if (lane == 0) red[0] = tv;
    }
    __syncthreads();
    const float res = red[0];
    __syncthreads();
    return res;
}

__global__ void attn_kernel() {
    __shared__ float red[16];
    __shared__ int wcnt[16];
    __shared__ int woff[16];

    const int r = blockIdx.x;
    const int b = r >> 9, c = r & 511;
    const int d = threadIdx.x;
    const int lane = d & 31, wid = d >> 5;

    const float* S0 = g_S + ((size_t)b * M2 + c) * M2;
    const float* S1 = g_S + ((size_t)b * M2 + CCH + c) * M2;

    const float er = S0[d] - S1[CCH + d];
    const float ei = S0[CCH + d] + S1[d];

    const float mer = blkReduce(er, red, true);
    const float mei = blkReduce(ei, red, true);

    const float ar = mer - er;
    const float ai = mei - ei;
    const float s = ar * ar + ai * ai;

    const float smax = blkReduce(s, red, true);
    const float e = expf(s - smax);
    const float Z = blkReduce(e, red, false);
    const float w = e / Z;

    const bool keep = w > 1e-10f;
    const unsigned msk = __ballot_sync(0xffffffffu, keep);
    const int inpos = __popc(msk & ((1u << lane) - 1u));
    if (lane == 0) wcnt[wid] = __popc(msk);
    __syncthreads();
    if (d == 0) {
        int run = 0;
        #pragma unroll
        for (int i = 0; i < 16; i++) { woff[i] = run; run += wcnt[i]; }
        g_cnt[r] = run;
    }
    __syncthreads();
    if (keep) {
        const int pos = woff[wid] + inpos;
        g_idx[(size_t)r * CCH + pos] = (unsigned short)d;
        g_w[(size_t)r * CCH + pos] = w;
    }
}

// =======================================================================
// Kernel C: out = gamma * (sparse attention @ q) + x
// =======================================================================
__global__ __launch_bounds__(256) void apply_kernel(const float* __restrict__ x,
                                                    const float* __restrict__ gamma,
                                                    float* __restrict__ out) {
    const int r = blockIdx.x;
    const int b = r >> 9, c = r & 511;
    const int n = blockIdx.y * 1024 + threadIdx.x * 4;

    const int cnt = g_cnt[r];
    const float g = gamma[0];
    const size_t imagOff = (size_t)BATCH * CCH * KDIM;
    const float* xr = x;
    const float* xi = x + imagOff;

    float4 ar = make_float4(0.f, 0.f, 0.f, 0.f);
    float4 ai = make_float4(0.f, 0.f, 0.f, 0.f);
    const size_t lbase = (size_t)r * CCH;

    for (int i = 0; i < cnt; i++) {
        const int dch = g_idx[lbase + i];
        const float w = g_w[lbase + i];
        const size_t q = ((size_t)b * CCH + dch) * KDIM + n;
        const float4 qr = *(const float4*)(xr + q);
        const float4 qi = *(const float4*)(xi + q);
        ar.x += w * qr.x; ar.y += w * qr.y; ar.z += w * qr.z; ar.w += w * qr.w;
        ai.x += w * qi.x; ai.y += w * qi.y; ai.z += w * qi.z; ai.w += w * qi.w;
    }

    const size_t o = ((size_t)b * CCH + c) * KDIM + n;
    const float4 xrv = *(const float4*)(xr + o);
    const float4 xiv = *(const float4*)(xi + o);
    float4 orr = make_float4(g * ar.x + xrv.x, g * ar.y + xrv.y,
                             g * ar.z + xrv.z, g * ar.w + xrv.w);
    float4 oii = make_float4(g * ai.x + xiv.x, g * ai.y + xiv.y,
                             g * ai.z + xiv.z, g * ai.w + xiv.w);
    *(float4*)(out + o) = orr;
    *(float4*)(out + imagOff + o) = oii;
}

// =======================================================================
extern "C" void kernel_launch(void* const* d_in, const int* in_sizes, int n_in,
                              void* d_out, int out_size) {
    const float* x = (const float*)d_in[0];
    const float* gamma = (const float*)d_in[1];
    float* out = (float*)d_out;

    const int SMEM_DYN = 1024 + NSTAGES * STAGE_BYTES + 128;   // ~197.8 KB
    cudaFuncSetAttribute(syrk_tc_kernel, cudaFuncAttributeMaxDynamicSharedMemorySize, SMEM_DYN);

    probe_kernel<<<1, 1>>>();
    split_kernel<<<(BATCH * 1024 * 1024) / 256, 256>>>(x);
    syrk_tc_kernel<<<dim3(NTILES * (NTILES + 1) / 2, BATCH), 128, SMEM_DYN>>>();
    syrk_simt_kernel<<<dim3(NTILES * (NTILES + 1) / 2, BATCH), 256>>>(x);
    attn_kernel<<<BATCH * CCH, 512>>>();
    apply_kernel<<<dim3(BATCH * CCH, 4), 256>>>(x, gamma, out);
}